// round 10
// baseline (speedup 1.0000x reference)
#include <cuda_runtime.h>
#include <math.h>

// Problem constants
#define BN    8192
#define NINPC 256
#define NHIDC 1024
#define NBO   8
#define BSO   128

// ---------------------------------------------------------------------------
// Scratch (device globals — no allocation allowed in kernel_launch)
// ---------------------------------------------------------------------------
__device__ float g_kk  [BN * 64];        // x @ Wk1[1]
__device__ float g_v1  [BN * 512];       // x @ Wv1[1]
__device__ float g_q   [BN * 512];       // hq @ Wq1  (b, k*64+n)
__device__ float g_s   [BN * 8];         // sigmoid(l1)
__device__ float g_mask[BN * 8];         // top-k mask per block
__device__ float g_gx  [BN * 8 * 384];   // GRU input gates
__device__ float g_gh  [BN * 8 * 384];   // GRU hidden gates
__device__ float g_hn  [BN * 1024];      // hx_new (pre-att)
__device__ float g_q2  [BN * 512];
__device__ float g_k2  [BN * 512];
__device__ float g_v2  [BN * 512];
__device__ float g_o   [BN * 512];       // attention-2 output

// ---------------------------------------------------------------------------
// Generic 64x64 fp32 tiled GEMM, BK=16, 256 threads, 4x4 micro-tile.
// Batched over blockIdx.z:
//   A element  = A[z*aZoff  + row*lda + k]   (block-diagonal column slice)
//   B element  = B[z*bZstr  + k*ldb  + n]
//   C element  = C[z*cZoff  + row*ldc + n]
// mode 0: C = acc
// mode 1: C = sv[row*8+z]*acc + bias[z*biasStride+n]   (gx epilogue)
// mode 2: C = acc + bias[z*biasStride+n]               (gh epilogue)
// All dims assumed: M%64==0, N%64==0, K%16==0 (true for every call here).
// ---------------------------------------------------------------------------
__global__ void gemm_tile(const float* __restrict__ A, int lda, int aZoff,
                          const float* __restrict__ Bm, int ldb, long bZstr,
                          float* __restrict__ C, int ldc, int cZoff,
                          int K, int mode,
                          const float* __restrict__ sv,
                          const float* __restrict__ bias, int biasStride)
{
    __shared__ float As[16][68];   // transposed A tile, padded
    __shared__ float Bs[16][64];

    const int z = blockIdx.z;
    const float* Az = A + (long)z * aZoff;
    const float* Bz = Bm + (long)z * bZstr;
    float*       Cz = C + (long)z * cZoff;

    const int m0 = blockIdx.y * 64;
    const int n0 = blockIdx.x * 64;
    const int tid = threadIdx.x;
    const int tx = tid & 15, ty = tid >> 4;
    const int arow = tid >> 2, ak = (tid & 3) << 2;
    const int bk = tid >> 4,  bn = (tid & 15) << 2;

    float acc[4][4] = {};

    for (int k0 = 0; k0 < K; k0 += 16) {
        float4 a4 = *(const float4*)(Az + (long)(m0 + arow) * lda + k0 + ak);
        float4 b4 = *(const float4*)(Bz + (long)(k0 + bk) * ldb + n0 + bn);
        __syncthreads();
        As[ak + 0][arow] = a4.x;
        As[ak + 1][arow] = a4.y;
        As[ak + 2][arow] = a4.z;
        As[ak + 3][arow] = a4.w;
        *(float4*)&Bs[bk][bn] = b4;
        __syncthreads();
#pragma unroll
        for (int kk = 0; kk < 16; kk++) {
            float4 av = *(const float4*)&As[kk][ty * 4];
            float4 bv = *(const float4*)&Bs[kk][tx * 4];
            float a_[4] = {av.x, av.y, av.z, av.w};
            float b_[4] = {bv.x, bv.y, bv.z, bv.w};
#pragma unroll
            for (int i = 0; i < 4; i++)
#pragma unroll
                for (int j = 0; j < 4; j++)
                    acc[i][j] += a_[i] * b_[j];
        }
    }

#pragma unroll
    for (int i = 0; i < 4; i++) {
        const int r = m0 + ty * 4 + i;
        float vals[4];
#pragma unroll
        for (int j = 0; j < 4; j++) {
            float v = acc[i][j];
            const int n = n0 + tx * 4 + j;
            if (mode == 1)      v = sv[(long)r * 8 + z] * v + bias[z * biasStride + n];
            else if (mode == 2) v = v + bias[z * biasStride + n];
            vals[j] = v;
        }
        float4 o4 = make_float4(vals[0], vals[1], vals[2], vals[3]);
        *(float4*)(Cz + (long)r * ldc + n0 + tx * 4) = o4;
    }
}

// ---------------------------------------------------------------------------
// l1 score, sigmoid, and top-k mask.  One thread per (b,k); 8 threads per b
// aligned within a warp so the 8 scores can be exchanged via shuffle.
// Reference: top_k on null_score p0 = sigmoid(-l1) picks 4 LARGEST p0 (ties ->
// lower index) and masks them 0.  Equivalent rank rule on l1:
//   rank_k = #{ j : l1[j] < l1[k]  ||  (l1[j]==l1[k] && j<k) },  mask = rank>=4
// ---------------------------------------------------------------------------
__global__ void score_mask_kernel()
{
    const int idx = blockIdx.x * blockDim.x + threadIdx.x;   // 0 .. BN*8-1
    const int b = idx >> 3, k = idx & 7;
    const float* q  = g_q  + (long)b * 512 + k * 64;
    const float* kk = g_kk + (long)b * 64;
    float l = 0.f;
#pragma unroll
    for (int d = 0; d < 64; d++) l += q[d] * kk[d];
    l *= 0.125f;

    const int base = (threadIdx.x & 31) & ~7;
    int cnt = 0;
#pragma unroll
    for (int j = 0; j < 8; j++) {
        float lj = __shfl_sync(0xFFFFFFFFu, l, base + j);
        if (lj < l || (lj == l && j < k)) cnt++;
    }
    g_mask[idx] = (cnt < 4) ? 0.f : 1.f;
    g_s[idx]    = 1.f / (1.f + expf(-l));
}

// ---------------------------------------------------------------------------
// GRU elementwise: hx_new = (1-z)*n + z*h
// ---------------------------------------------------------------------------
__global__ void gru_kernel(const float* __restrict__ hx)
{
    const long idx = (long)blockIdx.x * blockDim.x + threadIdx.x; // BN*1024
    const int  e   = (int)(idx & 127);
    const long bk  = idx >> 7;                                    // b*8+k
    const float* gx = g_gx + bk * 384;
    const float* gh = g_gh + bk * 384;
    const float xr = gx[e], xz = gx[e + 128], xn = gx[e + 256];
    const float hr = gh[e], hz = gh[e + 128], hn = gh[e + 256];
    const float h  = hx[idx];
    const float r  = 1.f / (1.f + expf(-(xr + hr)));
    const float zz = 1.f / (1.f + expf(-(xz + hz)));
    const float n  = tanhf(xn + r * hn);
    g_hn[idx] = (1.f - zz) * n + zz * h;
}

// ---------------------------------------------------------------------------
// Second attention: per b, 4 heads x 8 query-blocks x 8 key-blocks, dim 16.
// One warp per b; one lane per (q-block, head).
// ---------------------------------------------------------------------------
__global__ void attn2_kernel()
{
    const int gwarp = (blockIdx.x * blockDim.x + threadIdx.x) >> 5; // = b
    const int lane  = threadIdx.x & 31;
    const int qb = lane >> 2, h = lane & 3;
    const long boff = (long)gwarp * 512;

    float qv[16];
    const float* qp = g_q2 + boff + qb * 64 + h * 16;
#pragma unroll
    for (int i = 0; i < 16; i++) qv[i] = qp[i];

    float sc[8];
#pragma unroll
    for (int kb = 0; kb < 8; kb++) {
        const float* kp = g_k2 + boff + kb * 64 + h * 16;
        float d = 0.f;
#pragma unroll
        for (int i = 0; i < 16; i++) d += qv[i] * kp[i];
        sc[kb] = d * 0.25f;
    }
    float mx = sc[0];
#pragma unroll
    for (int kb = 1; kb < 8; kb++) mx = fmaxf(mx, sc[kb]);
    float den = 0.f;
#pragma unroll
    for (int kb = 0; kb < 8; kb++) { sc[kb] = expf(sc[kb] - mx); den += sc[kb]; }
    const float inv = 1.f / den;

    float o[16] = {};
#pragma unroll
    for (int kb = 0; kb < 8; kb++) {
        const float* vp = g_v2 + boff + kb * 64 + h * 16;
        const float w = sc[kb] * inv;
#pragma unroll
        for (int i = 0; i < 16; i++) o[i] += w * vp[i];
    }
    float* op = g_o + boff + qb * 64 + h * 16;
#pragma unroll
    for (int i = 0; i < 16; i++) op[i] = o[i];
}

// ---------------------------------------------------------------------------
// Final: dual GEMM o@(gate_w|fc_w), gated att, add to hx_new, masked blend,
// and write BOTH outputs.  M = BN*8 = 65536, K = 64, N = 128.
// ---------------------------------------------------------------------------
__global__ void final_kernel(const float* __restrict__ gw, const float* __restrict__ gb,
                             const float* __restrict__ fw, const float* __restrict__ fb,
                             const float* __restrict__ hx,
                             float* __restrict__ outHx, float* __restrict__ outMask)
{
    __shared__ float As[16][68];
    __shared__ float Gs[16][64];
    __shared__ float Fs[16][64];

    const int m0 = blockIdx.y * 64;
    const int n0 = blockIdx.x * 64;
    const int tid = threadIdx.x;
    const int tx = tid & 15, ty = tid >> 4;
    const int arow = tid >> 2, ak = (tid & 3) << 2;
    const int bk = tid >> 4,  bn = (tid & 15) << 2;

    float accG[4][4] = {}, accF[4][4] = {};

    for (int k0 = 0; k0 < 64; k0 += 16) {
        float4 a4 = *(const float4*)(g_o + (long)(m0 + arow) * 64 + k0 + ak);
        float4 g4 = *(const float4*)(gw + (long)(k0 + bk) * 128 + n0 + bn);
        float4 f4 = *(const float4*)(fw + (long)(k0 + bk) * 128 + n0 + bn);
        __syncthreads();
        As[ak + 0][arow] = a4.x;
        As[ak + 1][arow] = a4.y;
        As[ak + 2][arow] = a4.z;
        As[ak + 3][arow] = a4.w;
        *(float4*)&Gs[bk][bn] = g4;
        *(float4*)&Fs[bk][bn] = f4;
        __syncthreads();
#pragma unroll
        for (int kk = 0; kk < 16; kk++) {
            float4 av = *(const float4*)&As[kk][ty * 4];
            float4 gv = *(const float4*)&Gs[kk][tx * 4];
            float4 fv = *(const float4*)&Fs[kk][tx * 4];
            float a_[4] = {av.x, av.y, av.z, av.w};
            float g_[4] = {gv.x, gv.y, gv.z, gv.w};
            float f_[4] = {fv.x, fv.y, fv.z, fv.w};
#pragma unroll
            for (int i = 0; i < 4; i++)
#pragma unroll
                for (int j = 0; j < 4; j++) {
                    accG[i][j] += a_[i] * g_[j];
                    accF[i][j] += a_[i] * f_[j];
                }
        }
    }

#pragma unroll
    for (int i = 0; i < 4; i++) {
        const int r = m0 + ty * 4 + i;            // = b*8 + k
        const float m = g_mask[r];
        const long base = (long)r * 128 + n0 + tx * 4;
        float hv[4], mv[4];
#pragma unroll
        for (int j = 0; j < 4; j++) {
            const int n = n0 + tx * 4 + j;
            const float u = 1.f / (1.f + expf(-(accG[i][j] + gb[n])));
            const float t = tanhf(accF[i][j] + fb[n]);
            const float h2 = g_hn[base + j] + u * t;
            hv[j] = m * h2 + (1.f - m) * hx[base + j];
            mv[j] = m;
        }
        *(float4*)(outHx + base)   = make_float4(hv[0], hv[1], hv[2], hv[3]);
        *(float4*)(outMask + base) = make_float4(mv[0], mv[1], mv[2], mv[3]);
    }
}

// ---------------------------------------------------------------------------
// Host launcher — graph-capturable (kernel launches only)
// ---------------------------------------------------------------------------
extern "C" void kernel_launch(void* const* d_in, const int* in_sizes, int n_in,
                              void* d_out, int out_size)
{
    const float* inp    = (const float*)d_in[0];
    const float* hx     = (const float*)d_in[1];
    /* d_in[2] = step (unused) */
    const float* Wq1    = (const float*)d_in[3];
    const float* Wk1    = (const float*)d_in[4];
    const float* Wv1    = (const float*)d_in[5];
    const float* Wq2    = (const float*)d_in[6];
    const float* Wk2    = (const float*)d_in[7];
    const float* Wv2    = (const float*)d_in[8];
    const float* fc_w   = (const float*)d_in[9];
    const float* fc_b   = (const float*)d_in[10];
    const float* gate_w = (const float*)d_in[11];
    const float* gate_b = (const float*)d_in[12];
    const float* gru_wi = (const float*)d_in[13];
    const float* gru_wh = (const float*)d_in[14];
    const float* gru_bi = (const float*)d_in[15];
    const float* gru_bh = (const float*)d_in[16];

    float* outHx   = (float*)d_out;
    float* outMask = outHx + (long)BN * NHIDC;

    float *pkk, *pv1, *pq, *ps, *pgx, *pgh, *phn, *pq2, *pk2, *pv2;
    cudaGetSymbolAddress((void**)&pkk, g_kk);
    cudaGetSymbolAddress((void**)&pv1, g_v1);
    cudaGetSymbolAddress((void**)&pq,  g_q);
    cudaGetSymbolAddress((void**)&ps,  g_s);
    cudaGetSymbolAddress((void**)&pgx, g_gx);
    cudaGetSymbolAddress((void**)&pgh, g_gh);
    cudaGetSymbolAddress((void**)&phn, g_hn);
    cudaGetSymbolAddress((void**)&pq2, g_q2);
    cudaGetSymbolAddress((void**)&pk2, g_k2);
    cudaGetSymbolAddress((void**)&pv2, g_v2);

    // kk = x @ Wk1[1]            (8192,256)x(256,64)
    gemm_tile<<<dim3(1, BN / 64, 1), 256>>>(inp, NINPC, 0,
                                            Wk1 + 256 * 64, 64, 0,
                                            pkk, 64, 0, 256, 0, nullptr, nullptr, 0);
    // v1 = x @ Wv1[1]            (8192,256)x(256,512)
    gemm_tile<<<dim3(8, BN / 64, 1), 256>>>(inp, NINPC, 0,
                                            Wv1 + 256 * 512, 512, 0,
                                            pv1, 512, 0, 256, 0, nullptr, nullptr, 0);
    // q[k] = hq[k] @ Wq1[k]      batched z=8: (8192,128)x(128,64)
    gemm_tile<<<dim3(1, BN / 64, 8), 256>>>(hx, NHIDC, 128,
                                            Wq1, 64, 128 * 64,
                                            pq, 512, 64, 128, 0, nullptr, nullptr, 0);
    // l1, sigmoid, top-k mask
    score_mask_kernel<<<BN * 8 / 256, 256>>>();
    // gx[k] = s*(v1 @ gru_wi[k]) + bi[k]   batched z=8: (8192,512)x(512,384)
    gemm_tile<<<dim3(6, BN / 64, 8), 256>>>(pv1, 512, 0,
                                            gru_wi, 384, 512L * 384,
                                            pgx, 3072, 384, 512, 1, ps, gru_bi, 384);
    // gh[k] = hq[k] @ gru_wh[k] + bh[k]    batched z=8: (8192,128)x(128,384)
    gemm_tile<<<dim3(6, BN / 64, 8), 256>>>(hx, NHIDC, 128,
                                            gru_wh, 384, 128L * 384,
                                            pgh, 3072, 384, 128, 2, nullptr, gru_bh, 384);
    // GRU elementwise -> hx_new
    gru_kernel<<<BN * NHIDC / 256, 256>>>(hx);
    // q2/k2/v2 = hx_new[k] @ W*2[k]        batched z=8: (8192,128)x(128,64)
    gemm_tile<<<dim3(1, BN / 64, 8), 256>>>(phn, NHIDC, 128, Wq2, 64, 128 * 64,
                                            pq2, 512, 64, 128, 0, nullptr, nullptr, 0);
    gemm_tile<<<dim3(1, BN / 64, 8), 256>>>(phn, NHIDC, 128, Wk2, 64, 128 * 64,
                                            pk2, 512, 64, 128, 0, nullptr, nullptr, 0);
    gemm_tile<<<dim3(1, BN / 64, 8), 256>>>(phn, NHIDC, 128, Wv2, 64, 128 * 64,
                                            pv2, 512, 64, 128, 0, nullptr, nullptr, 0);
    // second attention -> o
    attn2_kernel<<<BN * 32 / 256, 256>>>();
    // dual GEMM + gating + masked blend + both outputs
    final_kernel<<<dim3(2, BN * 8 / 64), 256>>>(gate_w, gate_b, fc_w, fc_b,
                                                hx, outHx, outMask);
    (void)in_sizes; (void)n_in; (void)out_size;
}

// round 11
// speedup vs baseline: 2.2734x; 2.2734x over previous
#include <cuda_runtime.h>
#include <math.h>

#define BN    8192
#define NINPC 256
#define NHIDC 1024

// ---------------------------------------------------------------------------
// Scratch (device globals)
// ---------------------------------------------------------------------------
__device__ float g_kk  [BN * 64];
__device__ float g_v1  [BN * 512];        // tf32-rounded output of v1 GEMM
__device__ float g_q   [BN * 512];
__device__ float g_s   [BN * 8];
__device__ float g_mask[BN * 8];
__device__ float g_gx  [BN * 8 * 384];
__device__ float g_gh  [BN * 8 * 384];
__device__ float g_hn  [BN * 1024];       // exact hx_new
__device__ float g_hnr [BN * 1024];       // tf32-rounded hx_new
__device__ float g_qkv [BN * 8 * 192];    // fused q2|k2|v2
__device__ float g_o   [BN * 512];
// tf32-rounded operand copies
__device__ float g_xr  [BN * 256];
__device__ float g_hxr [BN * 1024];
__device__ float g_wv1r[256 * 512];
__device__ float g_wir [8 * 512 * 384];
__device__ float g_whr [8 * 128 * 384];
__device__ float g_w2r [8 * 128 * 192];

__device__ __forceinline__ unsigned f2tf32(float x) {
    unsigned u;
    asm("cvt.rna.tf32.f32 %0, %1;" : "=r"(u) : "f"(x));
    return u;
}
__device__ __forceinline__ unsigned smem_u32(const void* p) {
    unsigned a;
    asm("{ .reg .u64 t; cvta.to.shared.u64 t, %1; cvt.u32.u64 %0, t; }"
        : "=r"(a) : "l"(p));
    return a;
}
#define CP16(dst, src) \
    asm volatile("cp.async.cg.shared.global [%0], [%1], 16;" :: "r"(dst), "l"(src))
#define CP_COMMIT() asm volatile("cp.async.commit_group;")

// ---------------------------------------------------------------------------
// Elementwise tf32 rounding copy (float4 vectorized; n % 4 == 0)
// ---------------------------------------------------------------------------
__global__ void round_tf32(const float* __restrict__ src, float* __restrict__ dst, int n4)
{
    int i = blockIdx.x * blockDim.x + threadIdx.x;
    if (i < n4) {
        float4 v = ((const float4*)src)[i];
        v.x = __uint_as_float(f2tf32(v.x));
        v.y = __uint_as_float(f2tf32(v.y));
        v.z = __uint_as_float(f2tf32(v.z));
        v.w = __uint_as_float(f2tf32(v.w));
        ((float4*)dst)[i] = v;
    }
}

// Concatenate Wq2|Wk2|Wv2 (each (8,128,64)) -> (8,128,192), tf32-rounded
__global__ void build_w2(const float* __restrict__ q, const float* __restrict__ k,
                         const float* __restrict__ v, float* __restrict__ dst)
{
    int i = blockIdx.x * blockDim.x + threadIdx.x;   // 8*128*192
    if (i >= 8 * 128 * 192) return;
    int c = i % 192, r = (i / 192) % 128, z = i / (192 * 128);
    const float* src = (c < 64) ? q : ((c < 128) ? k : v);
    dst[i] = __uint_as_float(f2tf32(src[z * 8192 + r * 64 + (c & 63)]));
}

// ---------------------------------------------------------------------------
// tf32 tensor-core GEMM via mma.sync.m16n8k8, CTA tile 128 x NT, K-chunk 32,
// double-buffered cp.async.  Operands must already be tf32-rounded fp32.
//   A[z*aZoff + m*lda + k],  B[z*bZstr + k*ldb + n],  C[z*cZoff + m*ldc + n]
// MODE 0: C=acc   1: C=sv[m*8+z]*acc+bias[z*biasLd+n]   2: C=acc+bias
// MODE 3: C=round_tf32(acc)
// grid (BN/128, N/NT, Z), 256 threads (8 warps).
// ---------------------------------------------------------------------------
template<int NT, int WARPS_M, int MODE>
__global__ void __launch_bounds__(256)
gemm_tf32(const float* __restrict__ A, int lda, int aZoff,
          const float* __restrict__ B, int ldb, long bZstr,
          float* __restrict__ C, int ldc, long cZoff, int K,
          const float* __restrict__ sv, const float* __restrict__ bias, int biasLd)
{
    constexpr int ASTR = 36;                 // 32 + 4 pad (floats)
    constexpr int BSTR = NT + 4;
    constexpr int STAGE = 128 * ASTR + 32 * BSTR;   // floats per stage
    constexpr int WM = 128 / WARPS_M;        // 64 or 32
    constexpr int MF = WM / 16;              // 4 or 2
    constexpr int NF = 4;                    // WN = 32 always
    constexpr int BITER = NT / 32;           // B cp.async iters

    extern __shared__ unsigned dsm[];
    const unsigned sbase = smem_u32(dsm);

    const int tid = threadIdx.x, lane = tid & 31, wid = tid >> 5;
    const int warpM = wid % WARPS_M, warpN = wid / WARPS_M;
    const int m0 = blockIdx.x * 128, n0 = blockIdx.y * NT, z = blockIdx.z;
    const float* Az = A + (long)z * aZoff;
    const float* Bz = B + (long)z * bZstr;

    const int lr = lane >> 2, lc = lane & 3;       // A/C row, A col / B row

    float acc[MF][NF][4];
#pragma unroll
    for (int i = 0; i < MF; i++)
#pragma unroll
        for (int j = 0; j < NF; j++)
#pragma unroll
            for (int e = 0; e < 4; e++) acc[i][j][e] = 0.f;

    auto load_stage = [&](int buf, int k0) {
        const unsigned base = sbase + buf * STAGE * 4;
        const int ar = tid >> 3, ac4 = (tid & 7) * 4;
#pragma unroll
        for (int i = 0; i < 4; i++) {
            const int row = i * 32 + ar;
            CP16(base + (row * ASTR + ac4) * 4,
                 Az + (long)(m0 + row) * lda + k0 + ac4);
        }
        const unsigned bb = base + 128 * ASTR * 4;
#pragma unroll
        for (int i = 0; i < BITER; i++) {
            const int idx = i * 256 + tid;
            const int row = idx / (NT / 4), c4 = (idx % (NT / 4)) * 4;
            CP16(bb + (row * BSTR + c4) * 4,
                 Bz + (long)(k0 + row) * ldb + n0 + c4);
        }
        CP_COMMIT();
    };

    const int NITER = K / 32;
    load_stage(0, 0);

    for (int it = 0; it < NITER; it++) {
        if (it + 1 < NITER) {
            load_stage((it + 1) & 1, (it + 1) * 32);
            asm volatile("cp.async.wait_group 1;");
        } else {
            asm volatile("cp.async.wait_group 0;");
        }
        __syncthreads();

        const unsigned* Au = dsm + (it & 1) * STAGE;
        const unsigned* Bu = Au + 128 * ASTR;
#pragma unroll
        for (int s = 0; s < 4; s++) {
            const int kc = s * 8;
            unsigned af[MF][4];
#pragma unroll
            for (int mf = 0; mf < MF; mf++) {
                const int r0 = warpM * WM + mf * 16 + lr;
                af[mf][0] = Au[(r0)     * ASTR + kc + lc];
                af[mf][1] = Au[(r0 + 8) * ASTR + kc + lc];
                af[mf][2] = Au[(r0)     * ASTR + kc + lc + 4];
                af[mf][3] = Au[(r0 + 8) * ASTR + kc + lc + 4];
            }
            unsigned bf[NF][2];
#pragma unroll
            for (int nf = 0; nf < NF; nf++) {
                const int cb = warpN * 32 + nf * 8 + lr;
                bf[nf][0] = Bu[(kc + lc)     * BSTR + cb];
                bf[nf][1] = Bu[(kc + lc + 4) * BSTR + cb];
            }
#pragma unroll
            for (int mf = 0; mf < MF; mf++)
#pragma unroll
                for (int nf = 0; nf < NF; nf++)
                    asm volatile(
                        "mma.sync.aligned.m16n8k8.row.col.f32.tf32.tf32.f32 "
                        "{%0,%1,%2,%3}, {%4,%5,%6,%7}, {%8,%9}, {%0,%1,%2,%3};"
                        : "+f"(acc[mf][nf][0]), "+f"(acc[mf][nf][1]),
                          "+f"(acc[mf][nf][2]), "+f"(acc[mf][nf][3])
                        : "r"(af[mf][0]), "r"(af[mf][1]), "r"(af[mf][2]), "r"(af[mf][3]),
                          "r"(bf[nf][0]), "r"(bf[nf][1]));
        }
        __syncthreads();
    }

    // epilogue
    float* Cz = C + (long)z * cZoff;
    const float* bz = bias ? (bias + (long)z * biasLd) : nullptr;
#pragma unroll
    for (int mf = 0; mf < MF; mf++) {
        const int r = m0 + warpM * WM + mf * 16 + lr;
        float s0 = 1.f, s1 = 1.f;
        if (MODE == 1) { s0 = sv[(long)r * 8 + z]; s1 = sv[(long)(r + 8) * 8 + z]; }
#pragma unroll
        for (int nf = 0; nf < NF; nf++) {
            const int c = n0 + warpN * 32 + nf * 8 + lc * 2;
            float v0 = acc[mf][nf][0], v1 = acc[mf][nf][1];
            float v2 = acc[mf][nf][2], v3 = acc[mf][nf][3];
            if (MODE == 1) {
                v0 = s0 * v0 + bz[c]; v1 = s0 * v1 + bz[c + 1];
                v2 = s1 * v2 + bz[c]; v3 = s1 * v3 + bz[c + 1];
            } else if (MODE == 2) {
                v0 += bz[c]; v1 += bz[c + 1];
                v2 += bz[c]; v3 += bz[c + 1];
            } else if (MODE == 3) {
                v0 = __uint_as_float(f2tf32(v0)); v1 = __uint_as_float(f2tf32(v1));
                v2 = __uint_as_float(f2tf32(v2)); v3 = __uint_as_float(f2tf32(v3));
            }
            *(float2*)(Cz + (long)r * ldc + c)       = make_float2(v0, v1);
            *(float2*)(Cz + (long)(r + 8) * ldc + c) = make_float2(v2, v3);
        }
    }
}

// ---------------------------------------------------------------------------
// fp32 64x64 tiled GEMM (exact paths: kk, q)
// ---------------------------------------------------------------------------
__global__ void gemm_tile(const float* __restrict__ A, int lda, int aZoff,
                          const float* __restrict__ Bm, int ldb, long bZstr,
                          float* __restrict__ C, int ldc, int cZoff, int K)
{
    __shared__ float As[16][68];
    __shared__ float Bs[16][64];

    const int z = blockIdx.z;
    const float* Az = A + (long)z * aZoff;
    const float* Bz = Bm + (long)z * bZstr;
    float*       Cz = C + (long)z * cZoff;

    const int m0 = blockIdx.y * 64, n0 = blockIdx.x * 64;
    const int tid = threadIdx.x;
    const int tx = tid & 15, ty = tid >> 4;
    const int arow = tid >> 2, ak = (tid & 3) << 2;
    const int bk = tid >> 4,  bn = (tid & 15) << 2;

    float acc[4][4] = {};
    for (int k0 = 0; k0 < K; k0 += 16) {
        float4 a4 = *(const float4*)(Az + (long)(m0 + arow) * lda + k0 + ak);
        float4 b4 = *(const float4*)(Bz + (long)(k0 + bk) * ldb + n0 + bn);
        __syncthreads();
        As[ak + 0][arow] = a4.x; As[ak + 1][arow] = a4.y;
        As[ak + 2][arow] = a4.z; As[ak + 3][arow] = a4.w;
        *(float4*)&Bs[bk][bn] = b4;
        __syncthreads();
#pragma unroll
        for (int kk = 0; kk < 16; kk++) {
            float4 av = *(const float4*)&As[kk][ty * 4];
            float4 bv = *(const float4*)&Bs[kk][tx * 4];
            float a_[4] = {av.x, av.y, av.z, av.w};
            float b_[4] = {bv.x, bv.y, bv.z, bv.w};
#pragma unroll
            for (int i = 0; i < 4; i++)
#pragma unroll
                for (int j = 0; j < 4; j++)
                    acc[i][j] += a_[i] * b_[j];
        }
    }
#pragma unroll
    for (int i = 0; i < 4; i++)
        *(float4*)(Cz + (long)(m0 + ty * 4 + i) * ldc + n0 + tx * 4) =
            make_float4(acc[i][0], acc[i][1], acc[i][2], acc[i][3]);
}

// ---------------------------------------------------------------------------
// score / mask (exact fp32, rank-sensitive)
// ---------------------------------------------------------------------------
__global__ void score_mask_kernel()
{
    const int idx = blockIdx.x * blockDim.x + threadIdx.x;
    const int b = idx >> 3, k = idx & 7;
    const float4* q4 = (const float4*)(g_q + (long)b * 512 + k * 64);
    const float4* k4 = (const float4*)(g_kk + (long)b * 64);
    float l = 0.f;
#pragma unroll
    for (int i = 0; i < 16; i++) {
        float4 a = q4[i], c = k4[i];
        l += a.x * c.x + a.y * c.y + a.z * c.z + a.w * c.w;
    }
    l *= 0.125f;
    const int base = (threadIdx.x & 31) & ~7;
    int cnt = 0;
#pragma unroll
    for (int j = 0; j < 8; j++) {
        float lj = __shfl_sync(0xFFFFFFFFu, l, base + j);
        if (lj < l || (lj == l && j < k)) cnt++;
    }
    g_mask[idx] = (cnt < 4) ? 0.f : 1.f;
    g_s[idx]    = 1.f / (1.f + expf(-l));
}

// ---------------------------------------------------------------------------
// GRU elementwise -> g_hn (exact) and g_hnr (tf32-rounded for qkv GEMM)
// ---------------------------------------------------------------------------
__global__ void gru_kernel(const float* __restrict__ hx)
{
    const long idx = (long)blockIdx.x * blockDim.x + threadIdx.x;
    const int  e   = (int)(idx & 127);
    const long bk  = idx >> 7;
    const float* gx = g_gx + bk * 384;
    const float* gh = g_gh + bk * 384;
    const float xr = gx[e], xz = gx[e + 128], xn = gx[e + 256];
    const float hr = gh[e], hz = gh[e + 128], hn = gh[e + 256];
    const float h  = hx[idx];
    const float r  = 1.f / (1.f + expf(-(xr + hr)));
    const float zz = 1.f / (1.f + expf(-(xz + hz)));
    const float n  = tanhf(xn + r * hn);
    const float o  = (1.f - zz) * n + zz * h;
    g_hn[idx]  = o;
    g_hnr[idx] = __uint_as_float(f2tf32(o));
}

// ---------------------------------------------------------------------------
// Second attention, fused qkv layout (b, z, [q|k|v] 192)
// ---------------------------------------------------------------------------
__global__ void attn2_kernel()
{
    const int b = (blockIdx.x * blockDim.x + threadIdx.x) >> 5;
    const int lane = threadIdx.x & 31;
    const int qb = lane >> 2, h = lane & 3;
    const float* base = g_qkv + (long)b * 1536;

    float4 qv[4];
    const float4* qp = (const float4*)(base + qb * 192 + h * 16);
#pragma unroll
    for (int i = 0; i < 4; i++) qv[i] = qp[i];

    float sc[8];
#pragma unroll
    for (int kb = 0; kb < 8; kb++) {
        const float4* kp = (const float4*)(base + kb * 192 + 64 + h * 16);
        float d = 0.f;
#pragma unroll
        for (int i = 0; i < 4; i++) {
            float4 kv = kp[i];
            d += qv[i].x * kv.x + qv[i].y * kv.y + qv[i].z * kv.z + qv[i].w * kv.w;
        }
        sc[kb] = d * 0.25f;
    }
    float mx = sc[0];
#pragma unroll
    for (int kb = 1; kb < 8; kb++) mx = fmaxf(mx, sc[kb]);
    float den = 0.f;
#pragma unroll
    for (int kb = 0; kb < 8; kb++) { sc[kb] = expf(sc[kb] - mx); den += sc[kb]; }
    const float inv = 1.f / den;

    float4 o[4] = {};
#pragma unroll
    for (int kb = 0; kb < 8; kb++) {
        const float4* vp = (const float4*)(base + kb * 192 + 128 + h * 16);
        const float w = sc[kb] * inv;
#pragma unroll
        for (int i = 0; i < 4; i++) {
            float4 vv = vp[i];
            o[i].x += w * vv.x; o[i].y += w * vv.y;
            o[i].z += w * vv.z; o[i].w += w * vv.w;
        }
    }
    float4* op = (float4*)(g_o + (long)b * 512 + qb * 64 + h * 16);
#pragma unroll
    for (int i = 0; i < 4; i++) op[i] = o[i];
}

// ---------------------------------------------------------------------------
// Final: dual GEMM + gating + masked blend + both outputs
// ---------------------------------------------------------------------------
__global__ void final_kernel(const float* __restrict__ gw, const float* __restrict__ gb,
                             const float* __restrict__ fw, const float* __restrict__ fb,
                             const float* __restrict__ hx,
                             float* __restrict__ outHx, float* __restrict__ outMask)
{
    __shared__ float As[16][68];
    __shared__ float Gs[16][64];
    __shared__ float Fs[16][64];

    const int m0 = blockIdx.y * 64, n0 = blockIdx.x * 64;
    const int tid = threadIdx.x;
    const int tx = tid & 15, ty = tid >> 4;
    const int arow = tid >> 2, ak = (tid & 3) << 2;
    const int bk = tid >> 4,  bn = (tid & 15) << 2;

    float accG[4][4] = {}, accF[4][4] = {};
    for (int k0 = 0; k0 < 64; k0 += 16) {
        float4 a4 = *(const float4*)(g_o + (long)(m0 + arow) * 64 + k0 + ak);
        float4 g4 = *(const float4*)(gw + (long)(k0 + bk) * 128 + n0 + bn);
        float4 f4 = *(const float4*)(fw + (long)(k0 + bk) * 128 + n0 + bn);
        __syncthreads();
        As[ak + 0][arow] = a4.x; As[ak + 1][arow] = a4.y;
        As[ak + 2][arow] = a4.z; As[ak + 3][arow] = a4.w;
        *(float4*)&Gs[bk][bn] = g4;
        *(float4*)&Fs[bk][bn] = f4;
        __syncthreads();
#pragma unroll
        for (int kk = 0; kk < 16; kk++) {
            float4 av = *(const float4*)&As[kk][ty * 4];
            float4 gv = *(const float4*)&Gs[kk][tx * 4];
            float4 fv = *(const float4*)&Fs[kk][tx * 4];
            float a_[4] = {av.x, av.y, av.z, av.w};
            float g_[4] = {gv.x, gv.y, gv.z, gv.w};
            float f_[4] = {fv.x, fv.y, fv.z, fv.w};
#pragma unroll
            for (int i = 0; i < 4; i++)
#pragma unroll
                for (int j = 0; j < 4; j++) {
                    accG[i][j] += a_[i] * g_[j];
                    accF[i][j] += a_[i] * f_[j];
                }
        }
    }
#pragma unroll
    for (int i = 0; i < 4; i++) {
        const int r = m0 + ty * 4 + i;
        const float m = g_mask[r];
        const long base = (long)r * 128 + n0 + tx * 4;
        float hv[4], mv[4];
#pragma unroll
        for (int j = 0; j < 4; j++) {
            const int n = n0 + tx * 4 + j;
            const float u = 1.f / (1.f + expf(-(accG[i][j] + gb[n])));
            const float t = tanhf(accF[i][j] + fb[n]);
            const float h2 = g_hn[base + j] + u * t;
            hv[j] = m * h2 + (1.f - m) * hx[base + j];
            mv[j] = m;
        }
        *(float4*)(outHx + base)   = make_float4(hv[0], hv[1], hv[2], hv[3]);
        *(float4*)(outMask + base) = make_float4(mv[0], mv[1], mv[2], mv[3]);
    }
}

// ---------------------------------------------------------------------------
// Host launcher — graph-capturable
// ---------------------------------------------------------------------------
extern "C" void kernel_launch(void* const* d_in, const int* in_sizes, int n_in,
                              void* d_out, int out_size)
{
    const float* inp    = (const float*)d_in[0];
    const float* hx     = (const float*)d_in[1];
    const float* Wq1    = (const float*)d_in[3];
    const float* Wk1    = (const float*)d_in[4];
    const float* Wv1    = (const float*)d_in[5];
    const float* Wq2    = (const float*)d_in[6];
    const float* Wk2    = (const float*)d_in[7];
    const float* Wv2    = (const float*)d_in[8];
    const float* fc_w   = (const float*)d_in[9];
    const float* fc_b   = (const float*)d_in[10];
    const float* gate_w = (const float*)d_in[11];
    const float* gate_b = (const float*)d_in[12];
    const float* gru_wi = (const float*)d_in[13];
    const float* gru_wh = (const float*)d_in[14];
    const float* gru_bi = (const float*)d_in[15];
    const float* gru_bh = (const float*)d_in[16];

    float* outHx   = (float*)d_out;
    float* outMask = outHx + (long)BN * NHIDC;

    float *pkk, *pv1, *pq, *ps;
    float *pxr, *phxr, *pwv1r, *pwir, *pwhr, *pw2r, *phnr;
    cudaGetSymbolAddress((void**)&pkk,   g_kk);
    cudaGetSymbolAddress((void**)&pv1,   g_v1);
    cudaGetSymbolAddress((void**)&pq,    g_q);
    cudaGetSymbolAddress((void**)&ps,    g_s);
    cudaGetSymbolAddress((void**)&pxr,   g_xr);
    cudaGetSymbolAddress((void**)&phxr,  g_hxr);
    cudaGetSymbolAddress((void**)&pwv1r, g_wv1r);
    cudaGetSymbolAddress((void**)&pwir,  g_wir);
    cudaGetSymbolAddress((void**)&pwhr,  g_whr);
    cudaGetSymbolAddress((void**)&pw2r,  g_w2r);
    cudaGetSymbolAddress((void**)&phnr,  g_hnr);
    float *pgx, *pgh, *pqkv;
    cudaGetSymbolAddress((void**)&pgx,  g_gx);
    cudaGetSymbolAddress((void**)&pgh,  g_gh);
    cudaGetSymbolAddress((void**)&pqkv, g_qkv);

    // dynamic smem opt-in for the tensor GEMMs
    constexpr int SM128 = 2 * (128 * 36 + 32 * 132) * 4;   // 70656 B
    constexpr int SM64  = 2 * (128 * 36 + 32 * 68)  * 4;   // 54272 B
    cudaFuncSetAttribute(gemm_tf32<128, 2, 3>, cudaFuncAttributeMaxDynamicSharedMemorySize, SM128);
    cudaFuncSetAttribute(gemm_tf32<128, 2, 1>, cudaFuncAttributeMaxDynamicSharedMemorySize, SM128);
    cudaFuncSetAttribute(gemm_tf32<128, 2, 2>, cudaFuncAttributeMaxDynamicSharedMemorySize, SM128);
    cudaFuncSetAttribute(gemm_tf32<64, 4, 0>,  cudaFuncAttributeMaxDynamicSharedMemorySize, SM64);

    // ---- tf32 rounding copies ----
    auto rnd = [](const float* s, float* d, int n) {
        round_tf32<<<(n / 4 + 255) / 256, 256>>>(s, d, n / 4);
    };
    rnd(inp, pxr, BN * 256);
    rnd(hx, phxr, BN * 1024);
    rnd(Wv1 + 256 * 512, pwv1r, 256 * 512);
    rnd(gru_wi, pwir, 8 * 512 * 384);
    rnd(gru_wh, pwhr, 8 * 128 * 384);
    build_w2<<<(8 * 128 * 192 + 255) / 256, 256>>>(Wq2, Wk2, Wv2, pw2r);

    // ---- exact fp32 paths: kk, q ----
    gemm_tile<<<dim3(1, BN / 64, 1), 256>>>(inp, NINPC, 0, Wk1 + 256 * 64, 64, 0,
                                            pkk, 64, 0, 256);
    gemm_tile<<<dim3(1, BN / 64, 8), 256>>>(hx, NHIDC, 128, Wq1, 64, 128 * 64,
                                            pq, 512, 64, 128);

    // v1 = round(xr @ Wv1r)   (8192,256)x(256,512)
    gemm_tf32<128, 2, 3><<<dim3(BN / 128, 4, 1), 256, SM128>>>(
        pxr, 256, 0, pwv1r, 512, 0, pv1, 512, 0, 256, nullptr, nullptr, 0);

    score_mask_kernel<<<BN * 8 / 256, 256>>>();

    // gx = s*(v1 @ wi) + bi    (8192,512)x(512,384) x8
    gemm_tf32<128, 2, 1><<<dim3(BN / 128, 3, 8), 256, SM128>>>(
        pv1, 512, 0, pwir, 384, 512L * 384, pgx, 3072, 384, 512, ps, gru_bi, 384);
    // gh = hq @ wh + bh        (8192,128)x(128,384) x8
    gemm_tf32<128, 2, 2><<<dim3(BN / 128, 3, 8), 256, SM128>>>(
        phxr, NHIDC, 128, pwhr, 384, 128L * 384, pgh, 3072, 384, 128, nullptr, gru_bh, 384);

    gru_kernel<<<BN * NHIDC / 256, 256>>>(hx);

    // qkv = hn @ [Wq2|Wk2|Wv2] (8192,128)x(128,192) x8
    gemm_tf32<64, 4, 0><<<dim3(BN / 128, 3, 8), 256, SM64>>>(
        phnr, NHIDC, 128, pw2r, 192, 128L * 192, pqkv, 1536, 192, 128,
        nullptr, nullptr, 0);

    attn2_kernel<<<BN * 32 / 256, 256>>>();

    final_kernel<<<dim3(2, BN * 8 / 64), 256>>>(gate_w, gate_b, fc_w, fc_b,
                                                hx, outHx, outMask);
    (void)in_sizes; (void)n_in; (void)out_size;
}

// round 12
// speedup vs baseline: 2.3501x; 1.0337x over previous
#include <cuda_runtime.h>
#include <math.h>

#define BN    8192
#define NINPC 256
#define NHIDC 1024

// ---------------------------------------------------------------------------
// Scratch (device globals)
// ---------------------------------------------------------------------------
__device__ float g_kk  [BN * 64];
__device__ float g_v1  [BN * 512];        // tf32-rounded v1
__device__ float g_q   [BN * 512];
__device__ float g_s   [BN * 8];
__device__ float g_mask[BN * 8];
__device__ float g_gx  [BN * 8 * 384];    // GRU input gates (b,z,384)
__device__ float g_hn  [BN * 1024];       // exact hx_new (pre-att)
__device__ float g_hnr [BN * 1024];       // tf32-rounded hx_new
__device__ float g_qkv [BN * 8 * 192];    // fused q2|k2|v2
__device__ float g_o   [BN * 512];        // attention-2 output (tf32-rounded)
// rounded weights
__device__ float g_wv1r[256 * 512];
__device__ float g_wir [8 * 512 * 384];
__device__ float g_whr [8 * 128 * 384];
__device__ float g_w2r [8 * 128 * 192];
__device__ float g_gf  [64 * 256];        // interleaved [gate|fc] weights

__device__ __forceinline__ unsigned f2tf32(float x) {
    unsigned u;
    asm("cvt.rna.tf32.f32 %0, %1;" : "=r"(u) : "f"(x));
    return u;
}
__device__ __forceinline__ unsigned smem_u32(const void* p) {
    unsigned a;
    asm("{ .reg .u64 t; cvta.to.shared.u64 t, %1; cvt.u32.u64 %0, t; }"
        : "=r"(a) : "l"(p));
    return a;
}
#define CP16(dst, src) \
    asm volatile("cp.async.cg.shared.global [%0], [%1], 16;" :: "r"(dst), "l"(src))
#define CP_COMMIT() asm volatile("cp.async.commit_group;")
#define MMA_TF32(acc, a0, a1, a2, a3, b0, b1) \
    asm volatile( \
        "mma.sync.aligned.m16n8k8.row.col.f32.tf32.tf32.f32 " \
        "{%0,%1,%2,%3}, {%4,%5,%6,%7}, {%8,%9}, {%0,%1,%2,%3};" \
        : "+f"((acc)[0]), "+f"((acc)[1]), "+f"((acc)[2]), "+f"((acc)[3]) \
        : "r"(a0), "r"(a1), "r"(a2), "r"(a3), "r"(b0), "r"(b1))

// ---------------------------------------------------------------------------
// Elementwise tf32 rounding copy (weights only now)
// ---------------------------------------------------------------------------
__global__ void round_tf32(const float* __restrict__ src, float* __restrict__ dst, int n4)
{
    int i = blockIdx.x * blockDim.x + threadIdx.x;
    if (i < n4) {
        float4 v = ((const float4*)src)[i];
        v.x = __uint_as_float(f2tf32(v.x));
        v.y = __uint_as_float(f2tf32(v.y));
        v.z = __uint_as_float(f2tf32(v.z));
        v.w = __uint_as_float(f2tf32(v.w));
        ((float4*)dst)[i] = v;
    }
}

// Concatenate Wq2|Wk2|Wv2 (each (8,128,64)) -> (8,128,192), tf32-rounded
__global__ void build_w2(const float* __restrict__ q, const float* __restrict__ k,
                         const float* __restrict__ v, float* __restrict__ dst)
{
    int i = blockIdx.x * blockDim.x + threadIdx.x;
    if (i >= 8 * 128 * 192) return;
    int c = i % 192, r = (i / 192) % 128, z = i / (192 * 128);
    const float* src = (c < 64) ? q : ((c < 128) ? k : v);
    dst[i] = __uint_as_float(f2tf32(src[z * 8192 + r * 64 + (c & 63)]));
}

// Interleave gate_w/fc_w (64x128 each) -> (64, 256): cols (2n, 2n+1) = (gw, fw)
__global__ void build_gf(const float* __restrict__ gw, const float* __restrict__ fw,
                         float* __restrict__ dst)
{
    int i = blockIdx.x * blockDim.x + threadIdx.x;
    if (i >= 64 * 128) return;
    int k = i >> 7, n = i & 127;
    dst[k * 256 + 2 * n]     = __uint_as_float(f2tf32(gw[k * 128 + n]));
    dst[k * 256 + 2 * n + 1] = __uint_as_float(f2tf32(fw[k * 128 + n]));
}

// ---------------------------------------------------------------------------
// tf32 mma.sync GEMM, CTA tile 128 x NT, K-chunk 32, 2-stage cp.async.
//   A[z*aZoff + m*lda + k],  B[z*bZstr + k*ldb + n],  C[z*cZoff + m*ldc + n]
// CVTA: round A fragments in-register (A unrounded fp32 in gmem).
// MODE 0: C=acc  1: C=sv[m*8+z]*acc+bias  2: C=acc+bias  3: C=round(acc)
// ---------------------------------------------------------------------------
template<int NT, int WARPS_M, int MODE, bool CVTA>
__global__ void __launch_bounds__(256)
gemm_tf32(const float* __restrict__ A, int lda, int aZoff,
          const float* __restrict__ B, int ldb, long bZstr,
          float* __restrict__ C, int ldc, long cZoff, int K,
          const float* __restrict__ sv, const float* __restrict__ bias, int biasLd)
{
    constexpr int ASTR = 36;
    constexpr int BSTR = NT + 4;
    constexpr int STAGE = 128 * ASTR + 32 * BSTR;
    constexpr int WM = 128 / WARPS_M;
    constexpr int MF = WM / 16;
    constexpr int NF = 4;
    constexpr int BITER = NT / 32;

    extern __shared__ unsigned dsm[];
    const unsigned sbase = smem_u32(dsm);

    const int tid = threadIdx.x, lane = tid & 31, wid = tid >> 5;
    const int warpM = wid % WARPS_M, warpN = wid / WARPS_M;
    const int m0 = blockIdx.x * 128, n0 = blockIdx.y * NT, z = blockIdx.z;
    const float* Az = A + (long)z * aZoff;
    const float* Bz = B + (long)z * bZstr;
    const int lr = lane >> 2, lc = lane & 3;

    float acc[MF][NF][4];
#pragma unroll
    for (int i = 0; i < MF; i++)
#pragma unroll
        for (int j = 0; j < NF; j++)
#pragma unroll
            for (int e = 0; e < 4; e++) acc[i][j][e] = 0.f;

    auto load_stage = [&](int buf, int k0) {
        const unsigned base = sbase + buf * STAGE * 4;
        const int ar = tid >> 3, ac4 = (tid & 7) * 4;
#pragma unroll
        for (int i = 0; i < 4; i++) {
            const int row = i * 32 + ar;
            CP16(base + (row * ASTR + ac4) * 4,
                 Az + (long)(m0 + row) * lda + k0 + ac4);
        }
        const unsigned bb = base + 128 * ASTR * 4;
#pragma unroll
        for (int i = 0; i < BITER; i++) {
            const int idx = i * 256 + tid;
            const int row = idx / (NT / 4), c4 = (idx % (NT / 4)) * 4;
            CP16(bb + (row * BSTR + c4) * 4,
                 Bz + (long)(k0 + row) * ldb + n0 + c4);
        }
        CP_COMMIT();
    };

    const int NITER = K / 32;
    load_stage(0, 0);

    for (int it = 0; it < NITER; it++) {
        if (it + 1 < NITER) {
            load_stage((it + 1) & 1, (it + 1) * 32);
            asm volatile("cp.async.wait_group 1;");
        } else {
            asm volatile("cp.async.wait_group 0;");
        }
        __syncthreads();

        const unsigned* Au = dsm + (it & 1) * STAGE;
        const unsigned* Bu = Au + 128 * ASTR;
#pragma unroll
        for (int s = 0; s < 4; s++) {
            const int kc = s * 8;
            unsigned af[MF][4];
#pragma unroll
            for (int mf = 0; mf < MF; mf++) {
                const int r0 = warpM * WM + mf * 16 + lr;
                unsigned r_[4];
                r_[0] = Au[(r0)     * ASTR + kc + lc];
                r_[1] = Au[(r0 + 8) * ASTR + kc + lc];
                r_[2] = Au[(r0)     * ASTR + kc + lc + 4];
                r_[3] = Au[(r0 + 8) * ASTR + kc + lc + 4];
#pragma unroll
                for (int e = 0; e < 4; e++)
                    af[mf][e] = CVTA ? f2tf32(__uint_as_float(r_[e])) : r_[e];
            }
            unsigned bf[NF][2];
#pragma unroll
            for (int nf = 0; nf < NF; nf++) {
                const int cb = warpN * 32 + nf * 8 + lr;
                bf[nf][0] = Bu[(kc + lc)     * BSTR + cb];
                bf[nf][1] = Bu[(kc + lc + 4) * BSTR + cb];
            }
#pragma unroll
            for (int mf = 0; mf < MF; mf++)
#pragma unroll
                for (int nf = 0; nf < NF; nf++)
                    MMA_TF32(acc[mf][nf], af[mf][0], af[mf][1], af[mf][2], af[mf][3],
                             bf[nf][0], bf[nf][1]);
        }
        __syncthreads();
    }

    float* Cz = C + (long)z * cZoff;
    const float* bz = bias ? (bias + (long)z * biasLd) : nullptr;
#pragma unroll
    for (int mf = 0; mf < MF; mf++) {
        const int r = m0 + warpM * WM + mf * 16 + lr;
        float s0 = 1.f, s1 = 1.f;
        if (MODE == 1) { s0 = sv[(long)r * 8 + z]; s1 = sv[(long)(r + 8) * 8 + z]; }
#pragma unroll
        for (int nf = 0; nf < NF; nf++) {
            const int c = n0 + warpN * 32 + nf * 8 + lc * 2;
            float v0 = acc[mf][nf][0], v1 = acc[mf][nf][1];
            float v2 = acc[mf][nf][2], v3 = acc[mf][nf][3];
            if (MODE == 1) {
                v0 = s0 * v0 + bz[c]; v1 = s0 * v1 + bz[c + 1];
                v2 = s1 * v2 + bz[c]; v3 = s1 * v3 + bz[c + 1];
            } else if (MODE == 2) {
                v0 += bz[c]; v1 += bz[c + 1];
                v2 += bz[c]; v3 += bz[c + 1];
            } else if (MODE == 3) {
                v0 = __uint_as_float(f2tf32(v0)); v1 = __uint_as_float(f2tf32(v1));
                v2 = __uint_as_float(f2tf32(v2)); v3 = __uint_as_float(f2tf32(v3));
            }
            *(float2*)(Cz + (long)r * ldc + c)       = make_float2(v0, v1);
            *(float2*)(Cz + (long)(r + 8) * ldc + c) = make_float2(v2, v3);
        }
    }
}

// ---------------------------------------------------------------------------
// Fused gh GEMM + GRU.  Per CTA: 32 batch rows, one block z, N=384 (all
// gates), K=128.  gh tile staged in smem; epilogue reads gx/hx, writes hn/hnr.
// warps: 2 (M) x 4 (N=96 each); A fragments rounded in-register from raw hx.
// ---------------------------------------------------------------------------
__global__ void __launch_bounds__(256, 2)
gemm_gru(const float* __restrict__ hx, const float* __restrict__ whr,
         const float* __restrict__ bh)
{
    constexpr int ASTR = 36, BSTR = 388;
    constexpr int STAGE = 32 * ASTR + 32 * BSTR;   // 13568 floats

    extern __shared__ float smf[];
    const unsigned sbase = smem_u32(smf);

    const int tid = threadIdx.x, lane = tid & 31, wid = tid >> 5;
    const int warpM = wid & 1, warpN = wid >> 1;
    const int m0 = blockIdx.x * 32, z = blockIdx.y;
    const float* Az = hx + (long)m0 * 1024 + z * 128;
    const float* Bz = whr + (long)z * (128 * 384);
    const int lr = lane >> 2, lc = lane & 3;

    float acc[12][4];
#pragma unroll
    for (int i = 0; i < 12; i++)
#pragma unroll
        for (int e = 0; e < 4; e++) acc[i][e] = 0.f;

    auto load_stage = [&](int buf, int k0) {
        const unsigned base = sbase + buf * STAGE * 4;
        {   // A: 32 rows x 32 cols, 1 CP16/thread
            const int row = tid >> 3, c4 = (tid & 7) * 4;
            CP16(base + (row * ASTR + c4) * 4, Az + (long)row * 1024 + k0 + c4);
        }
        const unsigned bb = base + 32 * ASTR * 4;
#pragma unroll
        for (int i = 0; i < 12; i++) {   // B: 32 x 384
            const int idx = i * 256 + tid;
            const int row = idx / 96, c4 = (idx % 96) * 4;
            CP16(bb + (row * BSTR + c4) * 4, Bz + (long)(k0 + row) * 384 + c4);
        }
        CP_COMMIT();
    };

    load_stage(0, 0);
    for (int it = 0; it < 4; it++) {
        if (it < 3) {
            load_stage((it + 1) & 1, (it + 1) * 32);
            asm volatile("cp.async.wait_group 1;");
        } else {
            asm volatile("cp.async.wait_group 0;");
        }
        __syncthreads();

        const float* Af = smf + (it & 1) * STAGE;
        const float* Bf = Af + 32 * ASTR;
#pragma unroll
        for (int s = 0; s < 4; s++) {
            const int kc = s * 8;
            const int r0 = warpM * 16 + lr;
            const unsigned a0 = f2tf32(Af[(r0)     * ASTR + kc + lc]);
            const unsigned a1 = f2tf32(Af[(r0 + 8) * ASTR + kc + lc]);
            const unsigned a2 = f2tf32(Af[(r0)     * ASTR + kc + lc + 4]);
            const unsigned a3 = f2tf32(Af[(r0 + 8) * ASTR + kc + lc + 4]);
#pragma unroll
            for (int nf = 0; nf < 12; nf++) {
                const int cb = warpN * 96 + nf * 8 + lr;
                const unsigned b0 = __float_as_uint(Bf[(kc + lc)     * BSTR + cb]);
                const unsigned b1 = __float_as_uint(Bf[(kc + lc + 4) * BSTR + cb]);
                MMA_TF32(acc[nf], a0, a1, a2, a3, b0, b1);
            }
        }
        __syncthreads();
    }

    // stage gh (+bias) tile into smem [32][388]
    const float* bhz = bh + z * 384;
    {
        const int r0 = warpM * 16 + lr;
#pragma unroll
        for (int nf = 0; nf < 12; nf++) {
            const int c0 = warpN * 96 + nf * 8 + lc * 2;
            const float b0 = bhz[c0], b1 = bhz[c0 + 1];
            *(float2*)(smf + (r0)     * BSTR + c0) = make_float2(acc[nf][0] + b0, acc[nf][1] + b1);
            *(float2*)(smf + (r0 + 8) * BSTR + c0) = make_float2(acc[nf][2] + b0, acc[nf][3] + b1);
        }
    }
    __syncthreads();

    // GRU epilogue: 32 rows x 128 cols, float4 per task
    for (int t = tid; t < 1024; t += 256) {
        const int row = t >> 5, e = (t & 31) * 4;
        const long gxb = (long)(m0 + row) * 3072 + z * 384 + e;
        const float4 xr4 = *(const float4*)(g_gx + gxb);
        const float4 xz4 = *(const float4*)(g_gx + gxb + 128);
        const float4 xn4 = *(const float4*)(g_gx + gxb + 256);
        const float4 hr4 = *(const float4*)(smf + row * BSTR + e);
        const float4 hz4 = *(const float4*)(smf + row * BSTR + e + 128);
        const float4 hn4 = *(const float4*)(smf + row * BSTR + e + 256);
        const long hb = (long)(m0 + row) * 1024 + z * 128 + e;
        const float4 h4 = *(const float4*)(hx + hb);
        float4 o4, orr;
        {
            const float xr[4] = {xr4.x, xr4.y, xr4.z, xr4.w};
            const float xz[4] = {xz4.x, xz4.y, xz4.z, xz4.w};
            const float xn[4] = {xn4.x, xn4.y, xn4.z, xn4.w};
            const float hr[4] = {hr4.x, hr4.y, hr4.z, hr4.w};
            const float hz[4] = {hz4.x, hz4.y, hz4.z, hz4.w};
            const float hn[4] = {hn4.x, hn4.y, hn4.z, hn4.w};
            const float hh[4] = {h4.x, h4.y, h4.z, h4.w};
            float o[4], orf[4];
#pragma unroll
            for (int j = 0; j < 4; j++) {
                const float r  = 1.f / (1.f + expf(-(xr[j] + hr[j])));
                const float zz = 1.f / (1.f + expf(-(xz[j] + hz[j])));
                const float n  = tanhf(xn[j] + r * hn[j]);
                o[j]   = (1.f - zz) * n + zz * hh[j];
                orf[j] = __uint_as_float(f2tf32(o[j]));
            }
            o4  = make_float4(o[0], o[1], o[2], o[3]);
            orr = make_float4(orf[0], orf[1], orf[2], orf[3]);
        }
        *(float4*)(g_hn + hb)  = o4;
        *(float4*)(g_hnr + hb) = orr;
    }
}

// ---------------------------------------------------------------------------
// Final tf32 dual GEMM with fused gating / masked blend.
// A = g_o (65536 x 64), B = g_gf (64 x 256, (2n,2n+1)=(gate,fc)).
// CTA: M=128, NT=64 (32 output cols).  warps 4(M) x 2(N).
// ---------------------------------------------------------------------------
__global__ void __launch_bounds__(256)
final_tc(const float* __restrict__ gb, const float* __restrict__ fb,
         const float* __restrict__ hx,
         float* __restrict__ outHx, float* __restrict__ outMask)
{
    constexpr int ASTR = 36, BSTR = 68;
    constexpr int STAGE = 128 * ASTR + 32 * BSTR;   // 6784 floats

    extern __shared__ unsigned dsm[];
    const unsigned sbase = smem_u32(dsm);

    const int tid = threadIdx.x, lane = tid & 31, wid = tid >> 5;
    const int warpM = wid & 3, warpN = wid >> 2;
    const int m0 = blockIdx.x * 128, n0 = blockIdx.y * 64;
    const int lr = lane >> 2, lc = lane & 3;

    float acc[2][4][4];
#pragma unroll
    for (int i = 0; i < 2; i++)
#pragma unroll
        for (int j = 0; j < 4; j++)
#pragma unroll
            for (int e = 0; e < 4; e++) acc[i][j][e] = 0.f;

    auto load_stage = [&](int buf, int k0) {
        const unsigned base = sbase + buf * STAGE * 4;
        const int ar = tid >> 3, ac4 = (tid & 7) * 4;
#pragma unroll
        for (int i = 0; i < 4; i++) {
            const int row = i * 32 + ar;
            CP16(base + (row * ASTR + ac4) * 4,
                 g_o + (long)(m0 + row) * 64 + k0 + ac4);
        }
        const unsigned bb = base + 128 * ASTR * 4;
#pragma unroll
        for (int i = 0; i < 2; i++) {
            const int idx = i * 256 + tid;
            const int row = idx >> 4, c4 = (idx & 15) * 4;
            CP16(bb + (row * BSTR + c4) * 4,
                 g_gf + (long)(k0 + row) * 256 + n0 + c4);
        }
        CP_COMMIT();
    };

    load_stage(0, 0);
    for (int it = 0; it < 2; it++) {
        if (it == 0) {
            load_stage(1, 32);
            asm volatile("cp.async.wait_group 1;");
        } else {
            asm volatile("cp.async.wait_group 0;");
        }
        __syncthreads();
        const unsigned* Au = dsm + it * STAGE;
        const unsigned* Bu = Au + 128 * ASTR;
#pragma unroll
        for (int s = 0; s < 4; s++) {
            const int kc = s * 8;
            unsigned af[2][4];
#pragma unroll
            for (int mf = 0; mf < 2; mf++) {
                const int r0 = warpM * 32 + mf * 16 + lr;
                af[mf][0] = Au[(r0)     * ASTR + kc + lc];
                af[mf][1] = Au[(r0 + 8) * ASTR + kc + lc];
                af[mf][2] = Au[(r0)     * ASTR + kc + lc + 4];
                af[mf][3] = Au[(r0 + 8) * ASTR + kc + lc + 4];
            }
#pragma unroll
            for (int nf = 0; nf < 4; nf++) {
                const int cb = warpN * 32 + nf * 8 + lr;
                const unsigned b0 = Bu[(kc + lc)     * BSTR + cb];
                const unsigned b1 = Bu[(kc + lc + 4) * BSTR + cb];
#pragma unroll
                for (int mf = 0; mf < 2; mf++)
                    MMA_TF32(acc[mf][nf], af[mf][0], af[mf][1], af[mf][2], af[mf][3], b0, b1);
            }
        }
        __syncthreads();
    }

#pragma unroll
    for (int mf = 0; mf < 2; mf++) {
        const int r = m0 + warpM * 32 + mf * 16 + lr;
        const float ma = g_mask[r], mb = g_mask[r + 8];
#pragma unroll
        for (int nf = 0; nf < 4; nf++) {
            const int c = n0 + warpN * 32 + nf * 8 + lc * 2;
            const int n = c >> 1;
            const float gbv = gb[n], fbv = fb[n];
            {
                const float u = 1.f / (1.f + expf(-(acc[mf][nf][0] + gbv)));
                const float t = tanhf(acc[mf][nf][1] + fbv);
                const long a = (long)r * 128 + n;
                const float h2 = g_hn[a] + u * t;
                outHx[a]   = ma * h2 + (1.f - ma) * hx[a];
                outMask[a] = ma;
            }
            {
                const float u = 1.f / (1.f + expf(-(acc[mf][nf][2] + gbv)));
                const float t = tanhf(acc[mf][nf][3] + fbv);
                const long a = (long)(r + 8) * 128 + n;
                const float h2 = g_hn[a] + u * t;
                outHx[a]   = mb * h2 + (1.f - mb) * hx[a];
                outMask[a] = mb;
            }
        }
    }
}

// ---------------------------------------------------------------------------
// fp32 64x64 tiled GEMM (exact paths: kk, q)
// ---------------------------------------------------------------------------
__global__ void gemm_tile(const float* __restrict__ A, int lda, int aZoff,
                          const float* __restrict__ Bm, int ldb, long bZstr,
                          float* __restrict__ C, int ldc, int cZoff, int K)
{
    __shared__ float As[16][68];
    __shared__ float Bs[16][64];

    const int z = blockIdx.z;
    const float* Az = A + (long)z * aZoff;
    const float* Bz = Bm + (long)z * bZstr;
    float*       Cz = C + (long)z * cZoff;

    const int m0 = blockIdx.y * 64, n0 = blockIdx.x * 64;
    const int tid = threadIdx.x;
    const int tx = tid & 15, ty = tid >> 4;
    const int arow = tid >> 2, ak = (tid & 3) << 2;
    const int bk = tid >> 4,  bn = (tid & 15) << 2;

    float acc[4][4] = {};
    for (int k0 = 0; k0 < K; k0 += 16) {
        float4 a4 = *(const float4*)(Az + (long)(m0 + arow) * lda + k0 + ak);
        float4 b4 = *(const float4*)(Bz + (long)(k0 + bk) * ldb + n0 + bn);
        __syncthreads();
        As[ak + 0][arow] = a4.x; As[ak + 1][arow] = a4.y;
        As[ak + 2][arow] = a4.z; As[ak + 3][arow] = a4.w;
        *(float4*)&Bs[bk][bn] = b4;
        __syncthreads();
#pragma unroll
        for (int kk = 0; kk < 16; kk++) {
            float4 av = *(const float4*)&As[kk][ty * 4];
            float4 bv = *(const float4*)&Bs[kk][tx * 4];
            float a_[4] = {av.x, av.y, av.z, av.w};
            float b_[4] = {bv.x, bv.y, bv.z, bv.w};
#pragma unroll
            for (int i = 0; i < 4; i++)
#pragma unroll
                for (int j = 0; j < 4; j++)
                    acc[i][j] += a_[i] * b_[j];
        }
    }
#pragma unroll
    for (int i = 0; i < 4; i++)
        *(float4*)(Cz + (long)(m0 + ty * 4 + i) * ldc + n0 + tx * 4) =
            make_float4(acc[i][0], acc[i][1], acc[i][2], acc[i][3]);
}

// ---------------------------------------------------------------------------
// score / mask: one warp per batch row (exact fp32, rank-sensitive).
// lane = 4*k + p; p-quarter of the 64-dot, xor-tree reduce, rank via shfl.
// ---------------------------------------------------------------------------
__global__ void score_mask_kernel()
{
    const int b = (blockIdx.x * blockDim.x + threadIdx.x) >> 5;
    const int lane = threadIdx.x & 31;
    const int k = lane >> 2, p = lane & 3;

    const float4* q4 = (const float4*)(g_q + (long)b * 512 + k * 64 + p * 16);
    const float4* k4 = (const float4*)(g_kk + (long)b * 64 + p * 16);
    float l = 0.f;
#pragma unroll
    for (int i = 0; i < 4; i++) {
        float4 a = q4[i], c = k4[i];
        l += a.x * c.x + a.y * c.y + a.z * c.z + a.w * c.w;
    }
    l += __shfl_xor_sync(0xFFFFFFFFu, l, 1);
    l += __shfl_xor_sync(0xFFFFFFFFu, l, 2);
    l *= 0.125f;

    int cnt = 0;
#pragma unroll
    for (int j = 0; j < 8; j++) {
        float lj = __shfl_sync(0xFFFFFFFFu, l, (j << 2) | p);
        if (lj < l || (lj == l && j < k)) cnt++;
    }
    if (p == 0) {
        g_mask[b * 8 + k] = (cnt < 4) ? 0.f : 1.f;
        g_s[b * 8 + k]    = 1.f / (1.f + expf(-l));
    }
}

// ---------------------------------------------------------------------------
// Second attention; output tf32-rounded (feeds final_tc only)
// ---------------------------------------------------------------------------
__global__ void attn2_kernel()
{
    const int b = (blockIdx.x * blockDim.x + threadIdx.x) >> 5;
    const int lane = threadIdx.x & 31;
    const int qb = lane >> 2, h = lane & 3;
    const float* base = g_qkv + (long)b * 1536;

    float4 qv[4];
    const float4* qp = (const float4*)(base + qb * 192 + h * 16);
#pragma unroll
    for (int i = 0; i < 4; i++) qv[i] = qp[i];

    float sc[8];
#pragma unroll
    for (int kb = 0; kb < 8; kb++) {
        const float4* kp = (const float4*)(base + kb * 192 + 64 + h * 16);
        float d = 0.f;
#pragma unroll
        for (int i = 0; i < 4; i++) {
            float4 kv = kp[i];
            d += qv[i].x * kv.x + qv[i].y * kv.y + qv[i].z * kv.z + qv[i].w * kv.w;
        }
        sc[kb] = d * 0.25f;
    }
    float mx = sc[0];
#pragma unroll
    for (int kb = 1; kb < 8; kb++) mx = fmaxf(mx, sc[kb]);
    float den = 0.f;
#pragma unroll
    for (int kb = 0; kb < 8; kb++) { sc[kb] = expf(sc[kb] - mx); den += sc[kb]; }
    const float inv = 1.f / den;

    float4 o[4] = {};
#pragma unroll
    for (int kb = 0; kb < 8; kb++) {
        const float4* vp = (const float4*)(base + kb * 192 + 128 + h * 16);
        const float w = sc[kb] * inv;
#pragma unroll
        for (int i = 0; i < 4; i++) {
            float4 vv = vp[i];
            o[i].x += w * vv.x; o[i].y += w * vv.y;
            o[i].z += w * vv.z; o[i].w += w * vv.w;
        }
    }
    float4* op = (float4*)(g_o + (long)b * 512 + qb * 64 + h * 16);
#pragma unroll
    for (int i = 0; i < 4; i++) {
        float4 v = o[i];
        v.x = __uint_as_float(f2tf32(v.x));
        v.y = __uint_as_float(f2tf32(v.y));
        v.z = __uint_as_float(f2tf32(v.z));
        v.w = __uint_as_float(f2tf32(v.w));
        op[i] = v;
    }
}

// ---------------------------------------------------------------------------
// Host launcher — graph-capturable
// ---------------------------------------------------------------------------
extern "C" void kernel_launch(void* const* d_in, const int* in_sizes, int n_in,
                              void* d_out, int out_size)
{
    const float* inp    = (const float*)d_in[0];
    const float* hx     = (const float*)d_in[1];
    const float* Wq1    = (const float*)d_in[3];
    const float* Wk1    = (const float*)d_in[4];
    const float* Wv1    = (const float*)d_in[5];
    const float* Wq2    = (const float*)d_in[6];
    const float* Wk2    = (const float*)d_in[7];
    const float* Wv2    = (const float*)d_in[8];
    const float* fc_w   = (const float*)d_in[9];
    const float* fc_b   = (const float*)d_in[10];
    const float* gate_w = (const float*)d_in[11];
    const float* gate_b = (const float*)d_in[12];
    const float* gru_wi = (const float*)d_in[13];
    const float* gru_wh = (const float*)d_in[14];
    const float* gru_bi = (const float*)d_in[15];
    const float* gru_bh = (const float*)d_in[16];

    float* outHx   = (float*)d_out;
    float* outMask = outHx + (long)BN * NHIDC;

    float *pkk, *pv1, *pq, *ps, *pgx, *phnr, *pqkv;
    float *pwv1r, *pwir, *pwhr, *pw2r, *pgf;
    cudaGetSymbolAddress((void**)&pkk,   g_kk);
    cudaGetSymbolAddress((void**)&pv1,   g_v1);
    cudaGetSymbolAddress((void**)&pq,    g_q);
    cudaGetSymbolAddress((void**)&ps,    g_s);
    cudaGetSymbolAddress((void**)&pgx,   g_gx);
    cudaGetSymbolAddress((void**)&phnr,  g_hnr);
    cudaGetSymbolAddress((void**)&pqkv,  g_qkv);
    cudaGetSymbolAddress((void**)&pwv1r, g_wv1r);
    cudaGetSymbolAddress((void**)&pwir,  g_wir);
    cudaGetSymbolAddress((void**)&pwhr,  g_whr);
    cudaGetSymbolAddress((void**)&pw2r,  g_w2r);
    cudaGetSymbolAddress((void**)&pgf,   g_gf);

    constexpr int SM128 = 2 * (128 * 36 + 32 * 132) * 4;   // 70656 B
    constexpr int SM64  = 2 * (128 * 36 + 32 * 68)  * 4;   // 54272 B
    constexpr int SMGRU = 2 * (32 * 36 + 32 * 388)  * 4;   // 108544 B
    constexpr int SMFIN = 2 * (128 * 36 + 32 * 68)  * 4;   // 54272 B
    cudaFuncSetAttribute(gemm_tf32<128, 2, 3, true>,  cudaFuncAttributeMaxDynamicSharedMemorySize, SM128);
    cudaFuncSetAttribute(gemm_tf32<128, 2, 1, false>, cudaFuncAttributeMaxDynamicSharedMemorySize, SM128);
    cudaFuncSetAttribute(gemm_tf32<64, 4, 0, false>,  cudaFuncAttributeMaxDynamicSharedMemorySize, SM64);
    cudaFuncSetAttribute(gemm_gru, cudaFuncAttributeMaxDynamicSharedMemorySize, SMGRU);
    cudaFuncSetAttribute(final_tc, cudaFuncAttributeMaxDynamicSharedMemorySize, SMFIN);

    // ---- weight prep (tiny) ----
    auto rnd = [](const float* s, float* d, int n) {
        round_tf32<<<(n / 4 + 255) / 256, 256>>>(s, d, n / 4);
    };
    rnd(Wv1 + 256 * 512, pwv1r, 256 * 512);
    rnd(gru_wi, pwir, 8 * 512 * 384);
    rnd(gru_wh, pwhr, 8 * 128 * 384);
    build_w2<<<(8 * 128 * 192 + 255) / 256, 256>>>(Wq2, Wk2, Wv2, pw2r);
    build_gf<<<(64 * 128 + 255) / 256, 256>>>(gate_w, fc_w, pgf);

    // ---- exact fp32 paths: kk, q ----
    gemm_tile<<<dim3(1, BN / 64, 1), 256>>>(inp, NINPC, 0, Wk1 + 256 * 64, 64, 0,
                                            pkk, 64, 0, 256);
    gemm_tile<<<dim3(1, BN / 64, 8), 256>>>(hx, NHIDC, 128, Wq1, 64, 128 * 64,
                                            pq, 512, 64, 128);

    // v1 = round(inp @ Wv1r)   (8192,256)x(256,512), A rounded in-register
    gemm_tf32<128, 2, 3, true><<<dim3(BN / 128, 4, 1), 256, SM128>>>(
        inp, 256, 0, pwv1r, 512, 0, pv1, 512, 0, 256, nullptr, nullptr, 0);

    score_mask_kernel<<<BN * 32 / 256, 256>>>();

    // gx = s*(v1 @ wi) + bi    (8192,512)x(512,384) x8
    gemm_tf32<128, 2, 1, false><<<dim3(BN / 128, 3, 8), 256, SM128>>>(
        pv1, 512, 0, pwir, 384, 512L * 384, pgx, 3072, 384, 512, ps, gru_bi, 384);

    // fused gh GEMM + GRU -> g_hn / g_hnr
    gemm_gru<<<dim3(BN / 32, 8), 256, SMGRU>>>(hx, pwhr, gru_bh);

    // qkv = hnr @ [Wq2|Wk2|Wv2] (8192,128)x(128,192) x8
    gemm_tf32<64, 4, 0, false><<<dim3(BN / 128, 3, 8), 256, SM64>>>(
        phnr, NHIDC, 128, pw2r, 192, 128L * 192, pqkv, 1536, 192, 128,
        nullptr, nullptr, 0);

    attn2_kernel<<<BN * 32 / 256, 256>>>();

    // fused final: dual tf32 GEMM + gating + masked blend + both outputs
    final_tc<<<dim3(BN * 8 / 128, 4), 256, SMFIN>>>(gate_b, fc_b, hx, outHx, outMask);

    (void)in_sizes; (void)n_in; (void)out_size;
}